// round 17
// baseline (speedup 1.0000x reference)
#include <cuda_runtime.h>
#include <cuda_fp16.h>
#include <math.h>
#include <stdint.h>

typedef unsigned short U16;

// ---------------- problem constants ----------------
#define NHH   16
#define NOPE_ 128
#define ROPED 64
#define VD_   128
#define QLORA_ 1536
#define KVLORA_ 512
#define HDIM  2048
#define BB    2
#define SS    2048
#define QEXT  576
#define QHD   (NOPE_ + ROPED)  // 192
#define NCOMB 2176
#define NVALID 2112

// ---------------- scratch ----------------
__device__ U16 g_hs_s [(long)BB*SS*HDIM];
__device__ U16 g_wcomb_s[(long)NCOMB*HDIM];
__device__ U16 g_wqu_s[(long)NHH*QHD*QLORA_];              // pre-multiplied by q_ln_w
__device__ U16 g_wo_s [(long)HDIM*HDIM];
__device__ U16 g_wkvup_s[(long)NHH*256*KVLORA_];
__device__ U16 g_wabsT_s[(long)NHH*KVLORA_*NOPE_];
__device__ U16 g_qlckv_s[(long)BB*SS*NCOMB];
__device__ float g_rs[(long)BB*SS];
__device__ U16 g_q_s  [(long)BB*SS*NHH*QHD];
__device__ U16 g_ckvT_s[(long)BB*KVLORA_*SS];
__device__ U16 g_qext_s[(long)BB*NHH*SS*QEXT];
__device__ U16 g_sc_s  [(long)BB*NHH*SS*SS];
__device__ U16 g_out1_s[(long)BB*NHH*SS*KVLORA_];
__device__ U16 g_out2_s[(long)BB*SS*NHH*VD_];

// ================= helpers =================
__device__ __forceinline__ uint32_t smem_u32(const void* p) {
    uint32_t a;
    asm("{ .reg .u64 t; cvta.to.shared.u64 t, %1; cvt.u32.u64 %0, t; }" : "=r"(a) : "l"(p));
    return a;
}
__device__ __forceinline__ void cp16(uint32_t dst, const void* src) {
    asm volatile("cp.async.cg.shared.global [%0], [%1], 16;" :: "r"(dst), "l"(src));
}
#define CP_COMMIT() asm volatile("cp.async.commit_group;" ::: "memory")
#define CP_WAIT1()  asm volatile("cp.async.wait_group 1;" ::: "memory")

__device__ __forceinline__ void ldmx4(uint32_t* r, uint32_t addr) {
    asm volatile("ldmatrix.sync.aligned.m8n8.x4.shared.b16 {%0,%1,%2,%3}, [%4];"
                 : "=r"(r[0]), "=r"(r[1]), "=r"(r[2]), "=r"(r[3]) : "r"(addr));
}
__device__ __forceinline__ void mma16816(float* d, const uint32_t* a, const uint32_t* b) {
    asm volatile("mma.sync.aligned.m16n8k16.row.col.f32.f16.f16.f32 "
                 "{%0,%1,%2,%3}, {%4,%5,%6,%7}, {%8,%9}, {%0,%1,%2,%3};"
                 : "+f"(d[0]), "+f"(d[1]), "+f"(d[2]), "+f"(d[3])
                 : "r"(a[0]), "r"(a[1]), "r"(a[2]), "r"(a[3]), "r"(b[0]), "r"(b[1]));
}
__device__ __forceinline__ U16 tohalf(float v) {
    return __half_as_ushort(__float2half_rn(v));
}
__device__ __forceinline__ float fromhalf(U16 v) {
    return __half2float(__ushort_as_half(v));
}

// ================= fp16 warp-MMA GEMM (single x single) =================
#define ROWB 144
#define TILEB (128 * ROWB)
#define SGB   (2 * TILEB)
#define MSMEM (3 * SGB)
#define MSMEM_T (MSMEM + 128)     // + invf table

extern __shared__ char dsmem[];

__global__ void __launch_bounds__(256, 2)
mma_gemm(const U16* __restrict__ A, const U16* __restrict__ B,
         float* __restrict__ C, U16* __restrict__ Co,
         const float* __restrict__ rowScale,
         const int* __restrict__ posp, U16* __restrict__ qextp, int ropeMode,
         int K, int lda, int ldb, int ldc, int ncols,
         long sAb, long sAhh, long sBb, long sBhh, long sCb, long sChh,
         int zh, float alpha, int causalSkip, int causalK, int outMode)
{
    int z = blockIdx.z;
    long ao = (long)(z / zh) * sAb + (long)(z % zh) * sAhh;
    long bo = (long)(z / zh) * sBb + (long)(z % zh) * sBhh;
    long co = (long)(z / zh) * sCb + (long)(z % zh) * sChh;
    int by = blockIdx.y, bx = blockIdx.x;
    if (causalSkip && bx * 128 > by * 128 + 127) return;
    int Klim = causalK ? min(K, by * 128 + 128) : K;
    int nCh = Klim >> 6;

    int tid = threadIdx.x;
    int lane = tid & 31, wid = tid >> 5;
    int wm = wid & 1, wn = wid >> 1;

    uint32_t sb = smem_u32(dsmem);
    float* invf = (float*)(dsmem + MSMEM);
    if (ropeMode && tid < 32)
        invf[tid] = (float)exp(-((double)(2 * tid) / 64.0) * 13.815510557964274);

    const U16* gA = A + ao + (long)(by * 128) * lda;
    const U16* gB = B + bo + (long)(bx * 128) * ldb;

    uint32_t aoff[4], boff[2];
    {
        int ar = wm * 64 + (lane & 15);
        int ak = (lane >> 4) << 3;
        #pragma unroll
        for (int mt = 0; mt < 4; mt++)
            aoff[mt] = (uint32_t)((ar + mt * 16) * ROWB + (ak << 1));
        int br = wn * 32 + (lane & 7) + ((lane & 16) ? 8 : 0);
        int bk = (lane & 8) ? 8 : 0;
        #pragma unroll
        for (int np = 0; np < 2; np++)
            boff[np] = (uint32_t)((br + np * 16) * ROWB + (bk << 1));
    }

    float acc[4][4][4];
    #pragma unroll
    for (int mt = 0; mt < 4; mt++)
        #pragma unroll
        for (int nt = 0; nt < 4; nt++)
            #pragma unroll
            for (int r = 0; r < 4; r++) acc[mt][nt][r] = 0.f;

    auto issue = [&](uint32_t sbase, int k0) {
        #pragma unroll
        for (int q = 0; q < 4; q++) {
            int idx = (q << 8) + tid;
            int row = idx >> 3;
            int e0  = (idx & 7) << 3;
            uint32_t d = sbase + (uint32_t)(row * ROWB + (e0 << 1));
            cp16(d,         gA + (long)row * lda + k0 + e0);
            cp16(d + TILEB, gB + (long)row * ldb + k0 + e0);
        }
    };

    issue(sb, 0);
    CP_COMMIT();
    if (nCh > 1) issue(sb + SGB, 64);
    CP_COMMIT();

    int sc = 0;
    for (int c = 0; c < nCh; c++) {
        CP_WAIT1();
        __syncthreads();
        if (c + 2 < nCh) {
            int sn = sc + 2; if (sn >= 3) sn -= 3;
            issue(sb + sn * SGB, (c + 2) << 6);
        }
        CP_COMMIT();

        uint32_t sA_ = sb + sc * SGB;
        uint32_t sB_ = sA_ + TILEB;

        #pragma unroll
        for (int kh = 0; kh < 4; kh++) {
            uint32_t koffs = (uint32_t)(kh * 32);
            uint32_t ah[4][4], bh[2][4];
            #pragma unroll
            for (int mt = 0; mt < 4; mt++)
                ldmx4(ah[mt], sA_ + aoff[mt] + koffs);
            #pragma unroll
            for (int np = 0; np < 2; np++)
                ldmx4(bh[np], sB_ + boff[np] + koffs);
            #pragma unroll
            for (int mt = 0; mt < 4; mt++)
                #pragma unroll
                for (int nt = 0; nt < 4; nt++)
                    mma16816(acc[mt][nt], ah[mt], &bh[nt >> 1][(nt & 1) << 1]);
        }
        if (++sc == 3) sc = 0;
    }

    #pragma unroll
    for (int mt = 0; mt < 4; mt++) {
        int r0 = by * 128 + wm * 64 + mt * 16 + (lane >> 2);
        float s0 = alpha, s1 = alpha;
        if (rowScale) {
            s0 *= rowScale[r0];
            s1 *= rowScale[r0 + 8];
        }
        #pragma unroll
        for (int nt = 0; nt < 4; nt++) {
            int c0 = bx * 128 + wn * 32 + nt * 8 + ((lane & 3) << 1);
            if (c0 >= ncols) continue;
            float v00 = s0 * acc[mt][nt][0], v01 = s0 * acc[mt][nt][1];
            float v10 = s1 * acc[mt][nt][2], v11 = s1 * acc[mt][nt][3];
            if (ropeMode) {
                int cc = c0 % QHD;
                if (cc >= NOPE_) {
                    // rope pair i for rows r0 and r0+8 -> scatter to qext
                    int i = (cc - NOPE_) >> 1;
                    int h = c0 / QHD;
                    float fi = invf[i];
                    {
                        float p = (float)posp[r0];
                        float sn, cs; sincosf(p * fi, &sn, &cs);
                        int b = r0 / SS, s = r0 % SS;
                        long qb = ((long)(b * NHH + h) * SS + s) * QEXT + KVLORA_;
                        qextp[qb + i]      = tohalf(v00 * cs - v01 * sn);
                        qextp[qb + 32 + i] = tohalf(v01 * cs + v00 * sn);
                    }
                    {
                        int r1 = r0 + 8;
                        float p = (float)posp[r1];
                        float sn, cs; sincosf(p * fi, &sn, &cs);
                        int b = r1 / SS, s = r1 % SS;
                        long qb = ((long)(b * NHH + h) * SS + s) * QEXT + KVLORA_;
                        qextp[qb + i]      = tohalf(v10 * cs - v11 * sn);
                        qextp[qb + 32 + i] = tohalf(v11 * cs + v10 * sn);
                    }
                    continue;
                }
                // nope columns fall through to normal fp16 store
            }
            if (outMode == 0) {
                *(float2*)(C + co + (long)r0 * ldc + c0) = make_float2(v00, v01);
                *(float2*)(C + co + (long)(r0 + 8) * ldc + c0) = make_float2(v10, v11);
            } else {
                *(uint32_t*)(Co + co + (long)r0 * ldc + c0) =
                    (uint32_t)tohalf(v00) | ((uint32_t)tohalf(v01) << 16);
                *(uint32_t*)(Co + co + (long)(r0 + 8) * ldc + c0) =
                    (uint32_t)tohalf(v10) | ((uint32_t)tohalf(v11) << 16);
            }
        }
    }
}

// ---------------- fused multi-tensor fp32 -> fp16 convert ----------------
#define NSEG 6
struct SegTab {
    const float* src[NSEG];
    U16* dst[NSEG];
    long end[NSEG];
};

__global__ void convert_all_kernel(SegTab t, const float* __restrict__ w, int wseg, long total4)
{
    long i4 = (long)blockIdx.x * 256 + threadIdx.x;
    if (i4 >= total4) return;
    int s = 0;
    #pragma unroll
    for (int k = 0; k < NSEG - 1; k++) s += (i4 >= t.end[k]);
    long base4 = s ? t.end[s - 1] : 0;
    long off = (i4 - base4) * 4;
    float4 v = *(const float4*)(t.src[s] + off);
    if (s == wseg) {
        int k = (int)(off % QLORA_);
        v.x *= w[k]; v.y *= w[k + 1]; v.z *= w[k + 2]; v.w *= w[k + 3];
    }
    uint2 ov;
    ov.x = (uint32_t)tohalf(v.x) | ((uint32_t)tohalf(v.y) << 16);
    ov.y = (uint32_t)tohalf(v.z) | ((uint32_t)tohalf(v.w) << 16);
    *(uint2*)(t.dst[s] + off) = ov;
}

// ---------------- RMSNorm row scales ----------------
__global__ void rowscale_kernel(const U16* __restrict__ qlckv, float* __restrict__ rs)
{
    long ib = (long)blockIdx.x * NCOMB;
    int tid = threadIdx.x;
    int lane = tid & 31, wid = tid >> 5;
    float s = 0.f;
    #pragma unroll
    for (int j = 0; j < 6; j++) {
        uint32_t p = *(const uint32_t*)(qlckv + ib + j * 256 + tid * 2);
        float a = fromhalf((U16)(p & 0xffff));
        float b = fromhalf((U16)(p >> 16));
        s += a * a + b * b;
    }
    #pragma unroll
    for (int o = 16; o > 0; o >>= 1) s += __shfl_xor_sync(0xffffffffu, s, o);
    __shared__ float wr[4];
    if (lane == 0) wr[wid] = s;
    __syncthreads();
    if (tid == 0) {
        float tot = wr[0] + wr[1] + wr[2] + wr[3];
        rs[blockIdx.x] = rsqrtf(tot / (float)QLORA_ + 1e-6f);
    }
}

// ---------------- RoPE k ----------------
__global__ void rope_k_kernel(U16* __restrict__ qlckv, const int* __restrict__ pos)
{
    __shared__ float invf[32];
    if (threadIdx.x < 32)
        invf[threadIdx.x] = (float)exp(-((double)(2 * threadIdx.x) / 64.0) * 13.815510557964274);
    __syncthreads();
    int bs = blockIdx.x * blockDim.x + threadIdx.x;
    if (bs >= BB * SS) return;
    float p = (float)pos[bs];
    U16* x = qlckv + (long)bs * NCOMB + QLORA_ + KVLORA_;
    U16 tmp[64];
    #pragma unroll 8
    for (int i = 0; i < 32; i++) {
        float sn, cs;
        sincosf(p * invf[i], &sn, &cs);
        float x0 = fromhalf(x[2 * i]);
        float x1 = fromhalf(x[2 * i + 1]);
        tmp[i]      = tohalf(x0 * cs - x1 * sn);
        tmp[32 + i] = tohalf(x1 * cs + x0 * sn);
    }
    for (int j = 0; j < 64; j++) x[j] = tmp[j];
}

// ---------------- transposes ----------------
__global__ void transpose_wabs_kernel(const float* __restrict__ Wkv_up, U16* __restrict__ os)
{
    int idx = blockIdx.x * blockDim.x + threadIdx.x;
    if (idx >= NHH * KVLORA_ * NOPE_) return;
    int n = idx % NOPE_;
    int r = idx / NOPE_;
    int c = r % KVLORA_;
    int h = r / KVLORA_;
    os[idx] = tohalf(Wkv_up[((long)h * 256 + n) * KVLORA_ + c]);
}

__global__ void transpose_ckv_kernel(const U16* __restrict__ qlckv, U16* __restrict__ os)
{
    __shared__ U16 t[32][33];
    int b = blockIdx.z;
    int s0 = blockIdx.x * 32, c0 = blockIdx.y * 32;
    int x = threadIdx.x, y = threadIdx.y;
    for (int i = y; i < 32; i += 8)
        t[i][x] = qlckv[((long)b * SS + s0 + i) * NCOMB + QLORA_ + c0 + x];
    __syncthreads();
    for (int i = y; i < 32; i += 8)
        os[((long)b * KVLORA_ + c0 + i) * SS + s0 + x] = t[x][i];
}

// ---------------- causal softmax (register-resident rows) ----------------
__global__ void softmax_kernel(U16* __restrict__ sc)
{
    long row = blockIdx.x;
    int q = (int)(row % SS);
    long ob = row * (long)SS;
    int tid = threadIdx.x;
    int lane = tid & 31, wid = tid >> 5;
    int c0 = tid << 3;
    int blockEnd = ((q >> 7) + 1) << 7;
    __shared__ float wred[8];

    float v[8];
    bool active = (c0 < blockEnd);
    if (active) {
        uint4 pk = *(const uint4*)(sc + ob + c0);
        uint32_t w4[4] = {pk.x, pk.y, pk.z, pk.w};
        #pragma unroll
        for (int j = 0; j < 4; j++) {
            v[2 * j]     = fromhalf((U16)(w4[j] & 0xffff));
            v[2 * j + 1] = fromhalf((U16)(w4[j] >> 16));
        }
    }
    float mx = -1e30f;
    #pragma unroll
    for (int j = 0; j < 8; j++)
        if (active && c0 + j <= q) mx = fmaxf(mx, v[j]);
    #pragma unroll
    for (int o = 16; o > 0; o >>= 1) mx = fmaxf(mx, __shfl_xor_sync(0xffffffffu, mx, o));
    if (lane == 0) wred[wid] = mx;
    __syncthreads();
    mx = wred[lane & 7];
    #pragma unroll
    for (int o = 4; o > 0; o >>= 1) mx = fmaxf(mx, __shfl_xor_sync(0xffffffffu, mx, o));
    mx = __shfl_sync(0xffffffffu, mx, 0);

    float sum = 0.f;
    #pragma unroll
    for (int j = 0; j < 8; j++) {
        float e = (active && c0 + j <= q) ? __expf(v[j] - mx) : 0.f;
        v[j] = e;
        sum += e;
    }
    #pragma unroll
    for (int o = 16; o > 0; o >>= 1) sum += __shfl_xor_sync(0xffffffffu, sum, o);
    __syncthreads();
    if (lane == 0) wred[wid] = sum;
    __syncthreads();
    sum = wred[lane & 7];
    #pragma unroll
    for (int o = 4; o > 0; o >>= 1) sum += __shfl_xor_sync(0xffffffffu, sum, o);
    sum = __shfl_sync(0xffffffffu, sum, 0);
    float inv = 1.f / sum;

    if (active) {
        uint4 o4;
        uint32_t* w4 = (uint32_t*)&o4;
        #pragma unroll
        for (int j = 0; j < 4; j++)
            w4[j] = (uint32_t)tohalf(v[2 * j] * inv) |
                    ((uint32_t)tohalf(v[2 * j + 1] * inv) << 16);
        *(uint4*)(sc + ob + c0) = o4;
    }
}

// ---------------- host ----------------
static void launch_mma(const U16* A, const U16* B, float* C, U16* Co,
                       const float* rs, const int* posp, U16* qextp, int ropeMode,
                       int M, int Npad, int K, int lda, int ldb, int ldc, int ncols,
                       long sAb, long sAh, long sBb, long sBh, long sCb, long sCh,
                       int zh, int zcount, float alpha, int cSkip, int cK, int outMode)
{
    cudaFuncSetAttribute(mma_gemm, cudaFuncAttributeMaxDynamicSharedMemorySize, MSMEM_T);
    dim3 grid(Npad / 128, M / 128, zcount);
    mma_gemm<<<grid, 256, MSMEM_T>>>(A, B, C, Co, rs, posp, qextp, ropeMode,
        K, lda, ldb, ldc, ncols, sAb, sAh, sBb, sBh, sCb, sCh, zh, alpha, cSkip, cK, outMode);
}

extern "C" void kernel_launch(void* const* d_in, const int* in_sizes, int n_in,
                              void* d_out, int out_size)
{
    const float* hs      = (const float*)d_in[0];
    const int*   pos     = (const int*)  d_in[1];
    const float* Wq_down = (const float*)d_in[3];
    const float* q_ln_w  = (const float*)d_in[4];
    const float* Wq_up   = (const float*)d_in[5];
    const float* Wkv_down= (const float*)d_in[6];
    const float* Wkv_up  = (const float*)d_in[7];
    const float* Wo      = (const float*)d_in[8];
    float* out = (float*)d_out;

    U16 *hs_s, *wcomb_s, *wqu_s, *wo_s, *wkvup_s, *wabsT_s;
    U16 *qlckv_s, *q_s, *ckvT_s, *qext_s, *sc_s, *out1_s, *out2_s;
    float* rs;
    cudaGetSymbolAddress((void**)&hs_s, g_hs_s);
    cudaGetSymbolAddress((void**)&wcomb_s, g_wcomb_s);
    cudaGetSymbolAddress((void**)&wqu_s, g_wqu_s);
    cudaGetSymbolAddress((void**)&wo_s, g_wo_s);
    cudaGetSymbolAddress((void**)&wkvup_s, g_wkvup_s);
    cudaGetSymbolAddress((void**)&wabsT_s, g_wabsT_s);
    cudaGetSymbolAddress((void**)&qlckv_s, g_qlckv_s);
    cudaGetSymbolAddress((void**)&rs, g_rs);
    cudaGetSymbolAddress((void**)&q_s, g_q_s);
    cudaGetSymbolAddress((void**)&ckvT_s, g_ckvT_s);
    cudaGetSymbolAddress((void**)&qext_s, g_qext_s);
    cudaGetSymbolAddress((void**)&sc_s, g_sc_s);
    cudaGetSymbolAddress((void**)&out1_s, g_out1_s);
    cudaGetSymbolAddress((void**)&out2_s, g_out2_s);

    const int M = BB * SS;
    const float scale = 1.0f / sqrtf((float)QHD);

    // fused preprocessing converts (Wq_up gets q_ln_w folded: segment 3)
    {
        SegTab t;
        const long sz[NSEG] = {
            (long)BB * SS * HDIM, (long)QLORA_ * HDIM, (long)QEXT * HDIM,
            (long)NHH * QHD * QLORA_, (long)HDIM * HDIM, (long)NHH * 256 * KVLORA_ };
        const float* srcs[NSEG] = { hs, Wq_down, Wkv_down, Wq_up, Wo, Wkv_up };
        U16* dsts[NSEG] = { hs_s, wcomb_s, wcomb_s + (long)QLORA_ * HDIM, wqu_s, wo_s, wkvup_s };
        long acc = 0;
        for (int i = 0; i < NSEG; i++) {
            t.src[i] = srcs[i];
            t.dst[i] = dsts[i];
            acc += sz[i] / 4;
            t.end[i] = acc;
        }
        convert_all_kernel<<<(unsigned)((acc + 255) / 256), 256>>>(t, q_ln_w, 3, acc);
    }
    transpose_wabs_kernel<<<(NHH * KVLORA_ * NOPE_ + 255) / 256, 256>>>(Wkv_up, wabsT_s);

    // 1. [ql | ckv] = hs @ [Wq_down | Wkv_down]^T  [4096, 2176] fp16
    launch_mma(hs_s, wcomb_s, 0, qlckv_s, 0, 0, 0, 0,
               M, NCOMB, HDIM, HDIM, HDIM, NCOMB, NVALID,
               0,0,0,0,0,0, 1, 1, 1.f, 0, 0, 2);
    // 2. rmsnorm row scales
    rowscale_kernel<<<M, 128>>>(qlckv_s, rs);
    // 3. q = rs * (qlraw @ (Wq_up*w)^T), rope applied in epilogue -> qext rope cols,
    //    nope cols -> q_s
    launch_mma(qlckv_s, wqu_s, 0, q_s, rs, pos, qext_s, 1,
               M, NHH * QHD, QLORA_, NCOMB, QLORA_, NHH * QHD, NHH * QHD,
               0,0,0,0,0,0, 1, 1, 1.f, 0, 0, 2);
    // 4. RoPE k in place, then transpose ckv
    rope_k_kernel<<<(BB * SS + 255) / 256, 256>>>(qlckv_s, pos);
    {
        dim3 grid(SS / 32, KVLORA_ / 32, BB);
        transpose_ckv_kernel<<<grid, dim3(32, 8)>>>(qlckv_s, ckvT_s);
    }
    // 5. qext[:,0:512] = q_nope @ q_absorb
    launch_mma(q_s, wabsT_s, 0, qext_s, 0, 0, 0, 0,
               SS, KVLORA_, NOPE_, NHH * QHD, NOPE_, QEXT, KVLORA_,
               (long)SS * NHH * QHD, (long)QHD,
               0, (long)KVLORA_ * NOPE_,
               (long)NHH * SS * QEXT, (long)SS * QEXT,
               NHH, BB * NHH, 1.f, 0, 0, 2);
    // 6. scores = scale * qext @ ckv^T (B in combined buffer, ld 2176)
    launch_mma(qext_s, qlckv_s + QLORA_, 0, sc_s, 0, 0, 0, 0,
               SS, SS, QEXT, QEXT, NCOMB, SS, SS,
               (long)NHH * SS * QEXT, (long)SS * QEXT,
               (long)SS * NCOMB, 0,
               (long)NHH * SS * SS, (long)SS * SS,
               NHH, BB * NHH, scale, 1, 0, 2);
    // 7. softmax in place
    softmax_kernel<<<BB * NHH * SS, 256>>>(sc_s);
    // 8. out1 = probs @ ckvT, causal K-limit
    launch_mma(sc_s, ckvT_s, 0, out1_s, 0, 0, 0, 0,
               SS, KVLORA_, SS, SS, SS, KVLORA_, KVLORA_,
               (long)NHH * SS * SS, (long)SS * SS,
               (long)KVLORA_ * SS, 0,
               (long)NHH * SS * KVLORA_, (long)SS * KVLORA_,
               NHH, BB * NHH, 1.f, 0, 1, 2);
    // 9. out2 = out1 @ out_absorb^T
    launch_mma(out1_s, wkvup_s + (long)NOPE_ * KVLORA_, 0, out2_s, 0, 0, 0, 0,
               SS, VD_, KVLORA_, KVLORA_, KVLORA_, NHH * VD_, NHH * VD_,
               (long)NHH * SS * KVLORA_, (long)SS * KVLORA_,
               0, (long)256 * KVLORA_,
               (long)SS * NHH * VD_, (long)VD_,
               NHH, BB * NHH, 1.f, 0, 0, 2);
    // 10. final = out2 @ Wo^T [4096,2048] fp32 out
    launch_mma(out2_s, wo_s, out, 0, 0, 0, 0, 0,
               M, HDIM, NHH * VD_, NHH * VD_, NHH * VD_, HDIM, HDIM,
               0,0,0,0,0,0, 1, 1, 1.f, 0, 0, 0);
}